// round 7
// baseline (speedup 1.0000x reference)
#include <cuda_runtime.h>
#include <cuda_bf16.h>
#include <math.h>
#include <stdint.h>

#define D_IN 5
#define H0 128
#define H1 64

// scratch: 4 arrays of [1024][128] fp32 (hl_chg, hr_chg, hl_dg, hr_dg)
__device__ float g_hbuf[4 * 1024 * 128];
// W1 hi/lo bf16, n-major padded: [branch][hi/lo][64 rows][136 cols]
__device__ __align__(16) __nv_bfloat16 g_w1[2][2][64 * 136];
// pre-split gemm operands: [op A/B][hi/lo][1024*1024] bf16
// opA = A_chg in [m][k]; opB = A_gd in [k][n]
__device__ __align__(16) __nv_bfloat16 g_ops[2][2][1024 * 1024];

// ---------------------------------------------------------------------------
// PTX helpers (all architecture-portable: sm_80-level)
// ---------------------------------------------------------------------------
__device__ __forceinline__ void mma_bf16(
    float& d0, float& d1, float& d2, float& d3,
    uint32_t a0, uint32_t a1, uint32_t a2, uint32_t a3,
    uint32_t b0, uint32_t b1)
{
    asm volatile(
        "mma.sync.aligned.m16n8k16.row.col.f32.bf16.bf16.f32 "
        "{%0,%1,%2,%3}, {%4,%5,%6,%7}, {%8,%9}, {%0,%1,%2,%3};"
        : "+f"(d0), "+f"(d1), "+f"(d2), "+f"(d3)
        : "r"(a0), "r"(a1), "r"(a2), "r"(a3), "r"(b0), "r"(b1));
}

__device__ __forceinline__ void split2(float a, float b, uint32_t& hi, uint32_t& lo) {
    __nv_bfloat162 h = __float22bfloat162_rn(make_float2(a, b));
    float ra = a - __bfloat162float(h.x);
    float rb = b - __bfloat162float(h.y);
    __nv_bfloat162 l = __float22bfloat162_rn(make_float2(ra, rb));
    hi = *reinterpret_cast<uint32_t*>(&h);
    lo = *reinterpret_cast<uint32_t*>(&l);
}

__device__ __forceinline__ uint32_t smem_u32(const void* p) {
    uint32_t a;
    asm("{ .reg .u64 t; cvta.to.shared.u64 t, %1; cvt.u32.u64 %0, t; }"
        : "=r"(a) : "l"(p));
    return a;
}
__device__ __forceinline__ void cp_async16(uint32_t dst, const void* src) {
    asm volatile("cp.async.cg.shared.global [%0], [%1], 16;"
                 :: "r"(dst), "l"(src));
}
#define CP_COMMIT() asm volatile("cp.async.commit_group;" ::: "memory")
#define CP_WAIT(n)  asm volatile("cp.async.wait_group %0;" :: "n"(n) : "memory")

__device__ __forceinline__ void ldsm_x4(uint32_t& r0, uint32_t& r1,
                                        uint32_t& r2, uint32_t& r3, uint32_t a) {
    asm volatile("ldmatrix.sync.aligned.m8n8.x4.shared.b16 {%0,%1,%2,%3}, [%4];"
                 : "=r"(r0), "=r"(r1), "=r"(r2), "=r"(r3) : "r"(a));
}
__device__ __forceinline__ void ldsm_x4t(uint32_t& r0, uint32_t& r1,
                                         uint32_t& r2, uint32_t& r3, uint32_t a) {
    asm volatile("ldmatrix.sync.aligned.m8n8.x4.trans.shared.b16 {%0,%1,%2,%3}, [%4];"
                 : "=r"(r0), "=r"(r1), "=r"(r2), "=r"(r3) : "r"(a));
}
__device__ __forceinline__ uint32_t sw128(uint32_t bo) {
    return bo ^ ((bo >> 3) & 0x70);
}

// ---------------------------------------------------------------------------
// Kernel 1: precompute hl/hr for both branches (bias folded into hl)
// ---------------------------------------------------------------------------
__global__ void precompute_kernel(
    const float* __restrict__ X_ch, const float* __restrict__ X_g,
    const float* __restrict__ X_d,
    const float* __restrict__ W_chg0, const float* __restrict__ b_chg0,
    const float* __restrict__ W_dg0,  const float* __restrict__ b_dg0,
    int Nch, int Ng, int Nd)
{
    int a   = blockIdx.y;
    int row = blockIdx.x;
    int k   = threadIdx.x;

    const float* X; const float* W; const float* b = nullptr;
    int rows, woff;
    if (a == 0)      { X = X_ch; W = W_chg0; b = b_chg0; rows = Nch; woff = 0; }
    else if (a == 1) { X = X_g;  W = W_chg0;             rows = Ng;  woff = D_IN; }
    else if (a == 2) { X = X_g;  W = W_dg0;  b = b_dg0;  rows = Ng;  woff = 0; }
    else             { X = X_d;  W = W_dg0;              rows = Nd;  woff = D_IN; }
    if (row >= rows) return;

    float v = b ? b[k] : 0.0f;
#pragma unroll
    for (int d = 0; d < D_IN; d++)
        v = fmaf(X[row * D_IN + d], W[(woff + d) * H0 + k], v);
    g_hbuf[(a * 1024 + row) * H0 + k] = v;
}

// ---------------------------------------------------------------------------
// Kernel 1b: split W1 (both branches) into bf16 hi/lo, n-major padded [64][136]
// ---------------------------------------------------------------------------
__global__ void w1split_kernel(const float* __restrict__ W1a,
                               const float* __restrict__ W1b)
{
    int br = blockIdx.x;
    const float* W = br ? W1b : W1a;
    for (int i = threadIdx.x; i < 64 * 136; i += blockDim.x) {
        int n = i / 136, k = i % 136;
        float v = (k < H0) ? W[k * H1 + n] : 0.0f;
        __nv_bfloat16 h = __float2bfloat16(v);
        __nv_bfloat16 l = __float2bfloat16(v - __bfloat162float(h));
        g_w1[br][0][i] = h;
        g_w1[br][1][i] = l;
    }
}

// ---------------------------------------------------------------------------
// Kernel 2: pair MLP with warp-level bf16 MMA (3-product split), both branches
// in one grid (blockIdx.z). Inner loop ordered kt -> mh -> nt so only one
// m-half's A fragments are live at a time (low reg pressure -> 4 CTAs/SM).
// Epilogue emits f32 A and bf16 hi/lo into g_ops (opA [m][k], opB [k][n]).
// ---------------------------------------------------------------------------
#define SMEM_PAIR 54784

__global__ __launch_bounds__(128, 4) void pair_mlp_mma(
    const float* __restrict__ b1a, const float* __restrict__ Wra,
    const float* __restrict__ bra, float* __restrict__ Aa,
    const float* __restrict__ b1b, const float* __restrict__ Wrb,
    const float* __restrict__ brb, float* __restrict__ Ab,
    int R)
{
    extern __shared__ char smem[];
    __nv_bfloat16* sw1hi = (__nv_bfloat16*)smem;
    __nv_bfloat16* sw1lo = (__nv_bfloat16*)(smem + 17408);
    float* shr = (float*)(smem + 34816);
    float* shl = (float*)(smem + 52224);
    float* sb1 = (float*)(smem + 54272);
    float* swr = (float*)(smem + 54528);
    const uint32_t* w1hi32 = (const uint32_t*)sw1hi;
    const uint32_t* w1lo32 = (const uint32_t*)sw1lo;

    const int branch = blockIdx.z;
    const float* g_hl = g_hbuf + (branch ? 2 : 0) * 1024 * H0;
    const float* g_hr = g_hbuf + (branch ? 3 : 1) * 1024 * H0;
    const float* b1 = branch ? b1b : b1a;
    const float* Wr = branch ? Wrb : Wra;
    const float* br = branch ? brb : bra;
    float* A = branch ? Ab : Aa;
    __nv_bfloat16* opHi = g_ops[branch][0];
    __nv_bfloat16* opLo = g_ops[branch][1];

    const int t    = threadIdx.x;
    const int wid  = t >> 5;
    const int lane = t & 31;
    const int l0   = blockIdx.y * 4;
    const int rblk = blockIdx.x * 128;

    {
        const uint4* ghi = (const uint4*)g_w1[branch][0];
        const uint4* glo = (const uint4*)g_w1[branch][1];
        uint4* shi = (uint4*)sw1hi;
        uint4* slo = (uint4*)sw1lo;
        for (int i = t; i < 1088; i += 128) { shi[i] = ghi[i]; slo[i] = glo[i]; }
    }
    ((float4*)shl)[t] = ((const float4*)(g_hl + (size_t)l0 * H0))[t];
    if (t < H1) { sb1[t] = b1[t]; swr[t] = Wr[t]; }

    const float* shl_l = shl + wid * H0;
    const float brv = br[0];

    const int kq = (lane & 3) * 2;
    const int rq = lane >> 2;

    for (int riter = 0; riter < 4; riter++) {
        const int rbase = rblk + riter * 32;

        __syncthreads();
        for (int i = t; i < 1024; i += 128) {
            int row = i >> 5, c4 = i & 31;
            float4 v = ((const float4*)(g_hr + (size_t)(rbase + row) * H0))[c4];
            *(float4*)(shr + row * 136 + c4 * 4) = v;
        }
        __syncthreads();

        float acc[2][8][4];
#pragma unroll
        for (int mh = 0; mh < 2; mh++)
#pragma unroll
            for (int nt = 0; nt < 8; nt++)
#pragma unroll
                for (int c = 0; c < 4; c++) acc[mh][nt][c] = 0.0f;

#pragma unroll
        for (int kt = 0; kt < 8; kt++) {
            const int kk = kt * 16 + kq;
            const float2 y0 = *(const float2*)(shl_l + kk);
            const float2 y1 = *(const float2*)(shl_l + kk + 8);

#pragma unroll
            for (int mh = 0; mh < 2; mh++) {
                // ---- A fragments for this m-half only (8 live regs) ----
                uint32_t ahi[4], alo[4];
                {
                    int r_lo = mh * 16 + rq;
                    const float* p0 = shr + r_lo * 136 + kk;
                    const float* p1 = shr + (r_lo + 8) * 136 + kk;
                    float2 x00 = *(const float2*)p0;
                    float2 x01 = *(const float2*)(p0 + 8);
                    float2 x10 = *(const float2*)p1;
                    float2 x11 = *(const float2*)(p1 + 8);
                    split2(fmaxf(x00.x + y0.x, 0.f), fmaxf(x00.y + y0.y, 0.f),
                           ahi[0], alo[0]);
                    split2(fmaxf(x10.x + y0.x, 0.f), fmaxf(x10.y + y0.y, 0.f),
                           ahi[1], alo[1]);
                    split2(fmaxf(x01.x + y1.x, 0.f), fmaxf(x01.y + y1.y, 0.f),
                           ahi[2], alo[2]);
                    split2(fmaxf(x11.x + y1.x, 0.f), fmaxf(x11.y + y1.y, 0.f),
                           ahi[3], alo[3]);
                }
#pragma unroll
                for (int nt = 0; nt < 8; nt++) {
                    int w0 = (nt * 8 + rq) * 68 + kt * 8 + (lane & 3);
                    uint32_t bh0 = w1hi32[w0], bh1 = w1hi32[w0 + 4];
                    uint32_t bl0 = w1lo32[w0], bl1 = w1lo32[w0 + 4];
                    mma_bf16(acc[mh][nt][0], acc[mh][nt][1],
                             acc[mh][nt][2], acc[mh][nt][3],
                             ahi[0], ahi[1], ahi[2], ahi[3], bh0, bh1);
                    mma_bf16(acc[mh][nt][0], acc[mh][nt][1],
                             acc[mh][nt][2], acc[mh][nt][3],
                             ahi[0], ahi[1], ahi[2], ahi[3], bl0, bl1);
                    mma_bf16(acc[mh][nt][0], acc[mh][nt][1],
                             acc[mh][nt][2], acc[mh][nt][3],
                             alo[0], alo[1], alo[2], alo[3], bh0, bh1);
                }
            }
        }

        // epilogue: layer-2 relu/dot(Wr), quad reduce, ELU, store (f32 + bf16 split)
#pragma unroll
        for (int mh = 0; mh < 2; mh++) {
            float s0 = 0.0f, s1 = 0.0f;
#pragma unroll
            for (int nt = 0; nt < 8; nt++) {
                int j0 = nt * 8 + kq;
                float bb0 = sb1[j0], bb1 = sb1[j0 + 1];
                float ww0 = swr[j0], ww1 = swr[j0 + 1];
                s0 = fmaf(fmaxf(acc[mh][nt][0] + bb0, 0.f), ww0, s0);
                s0 = fmaf(fmaxf(acc[mh][nt][1] + bb1, 0.f), ww1, s0);
                s1 = fmaf(fmaxf(acc[mh][nt][2] + bb0, 0.f), ww0, s1);
                s1 = fmaf(fmaxf(acc[mh][nt][3] + bb1, 0.f), ww1, s1);
            }
            s0 += __shfl_xor_sync(0xffffffffu, s0, 1);
            s0 += __shfl_xor_sync(0xffffffffu, s0, 2);
            s1 += __shfl_xor_sync(0xffffffffu, s1, 1);
            s1 += __shfl_xor_sync(0xffffffffu, s1, 2);
            if ((lane & 3) == 0) {
                int r_lo = rbase + mh * 16 + rq;
                float x0 = s0 + brv;
                float x1 = s1 + brv;
                float e0 = (x0 > 0.0f) ? x0 : expm1f(x0);
                float e1 = (x1 > 0.0f) ? x1 : expm1f(x1);
                size_t rowoff = (size_t)(l0 + wid) * R;
                float* arow = A + rowoff;
                arow[r_lo]     = e0;
                arow[r_lo + 8] = e1;
                __nv_bfloat16 h0 = __float2bfloat16(e0);
                __nv_bfloat16 h1 = __float2bfloat16(e1);
                opHi[rowoff + r_lo]     = h0;
                opHi[rowoff + r_lo + 8] = h1;
                opLo[rowoff + r_lo]     = __float2bfloat16(e0 - __bfloat162float(h0));
                opLo[rowoff + r_lo + 8] = __float2bfloat16(e1 - __bfloat162float(h1));
            }
        }
    }
}

// ---------------------------------------------------------------------------
// Kernel 3: C = sigmoid(A @ B), bf16 3-product MMA, operands pre-split.
// (unchanged from R6 — 28.9us)
// ---------------------------------------------------------------------------
#define GS_STAGE 49152
#define GS_ALO   16384
#define GS_BHI   32768
#define GS_BLO   40960
#define SMEM_GEMM (2 * GS_STAGE)

__global__ __launch_bounds__(256, 1) void gemm_sigmoid_tc(
    float* __restrict__ C, int M, int N, int K)
{
    extern __shared__ char smem[];
    const uint32_t sb = smem_u32(smem);

    const __nv_bfloat16* gAhi = g_ops[0][0];
    const __nv_bfloat16* gAlo = g_ops[0][1];
    const __nv_bfloat16* gBhi = g_ops[1][0];
    const __nv_bfloat16* gBlo = g_ops[1][1];

    const int t    = threadIdx.x;
    const int wid  = t >> 5;
    const int lane = t & 31;
    const int m0 = blockIdx.y * 128, n0 = blockIdx.x * 64;
    const int wm = (wid >> 1) * 32;
    const int wn = (wid & 1) * 32;
    const int kq = (lane & 3) * 2;
    const int rq = lane >> 2;

    float acc[2][4][4];
#pragma unroll
    for (int mh = 0; mh < 2; mh++)
#pragma unroll
        for (int nt = 0; nt < 4; nt++)
#pragma unroll
            for (int c = 0; c < 4; c++) acc[mh][nt][c] = 0.0f;

    const int K64 = K >> 6;

    auto stage = [&](int kb, int buf) {
        uint32_t base = sb + buf * GS_STAGE;
#pragma unroll
        for (int i = t; i < 1024; i += 256) {
            int m = i >> 3, c = i & 7;
            uint32_t sw = sw128((uint32_t)(m * 128 + c * 16));
            size_t off = (size_t)(m0 + m) * K + kb * 64 + c * 8;
            cp_async16(base + sw, gAhi + off);
            cp_async16(base + GS_ALO + sw, gAlo + off);
        }
#pragma unroll
        for (int i = t; i < 512; i += 256) {
            int k = i >> 3, c = i & 7;
            uint32_t sw = sw128((uint32_t)(k * 128 + c * 16));
            size_t off = (size_t)(kb * 64 + k) * N + n0 + c * 8;
            cp_async16(base + GS_BHI + sw, gBhi + off);
            cp_async16(base + GS_BLO + sw, gBlo + off);
        }
    };

    stage(0, 0);
    CP_COMMIT();

    for (int kb = 0; kb < K64; kb++) {
        if (kb + 1 < K64) {
            stage(kb + 1, (kb + 1) & 1);
            CP_COMMIT();
            CP_WAIT(1);
        } else {
            CP_WAIT(0);
        }
        __syncthreads();

        uint32_t base = sb + (kb & 1) * GS_STAGE;
#pragma unroll
        for (int kt = 0; kt < 4; kt++) {
            uint32_t ahi[2][4], alo[2][4];
#pragma unroll
            for (int mh = 0; mh < 2; mh++) {
                int row = wm + mh * 16 + (lane & 15);
                uint32_t sw = sw128((uint32_t)(row * 128 + kt * 32 + (lane >> 4) * 16));
                ldsm_x4(ahi[mh][0], ahi[mh][1], ahi[mh][2], ahi[mh][3], base + sw);
                ldsm_x4(alo[mh][0], alo[mh][1], alo[mh][2], alo[mh][3],
                        base + GS_ALO + sw);
            }
            uint32_t bh[4][2], bl[4][2];
#pragma unroll
            for (int np = 0; np < 2; np++) {
                int krow = kt * 16 + (lane & 15);
                uint32_t sw = sw128((uint32_t)(krow * 128 + wn * 2 + np * 32
                                               + (lane >> 4) * 16));
                uint32_t r0, r1, r2, r3;
                ldsm_x4t(r0, r1, r2, r3, base + GS_BHI + sw);
                bh[np * 2][0] = r0; bh[np * 2][1] = r1;
                bh[np * 2 + 1][0] = r2; bh[np * 2 + 1][1] = r3;
                ldsm_x4t(r0, r1, r2, r3, base + GS_BLO + sw);
                bl[np * 2][0] = r0; bl[np * 2][1] = r1;
                bl[np * 2 + 1][0] = r2; bl[np * 2 + 1][1] = r3;
            }
#pragma unroll
            for (int nt = 0; nt < 4; nt++)
#pragma unroll
                for (int mh = 0; mh < 2; mh++) {
                    mma_bf16(acc[mh][nt][0], acc[mh][nt][1],
                             acc[mh][nt][2], acc[mh][nt][3],
                             ahi[mh][0], ahi[mh][1], ahi[mh][2], ahi[mh][3],
                             bh[nt][0], bh[nt][1]);
                    mma_bf16(acc[mh][nt][0], acc[mh][nt][1],
                             acc[mh][nt][2], acc[mh][nt][3],
                             ahi[mh][0], ahi[mh][1], ahi[mh][2], ahi[mh][3],
                             bl[nt][0], bl[nt][1]);
                    mma_bf16(acc[mh][nt][0], acc[mh][nt][1],
                             acc[mh][nt][2], acc[mh][nt][3],
                             alo[mh][0], alo[mh][1], alo[mh][2], alo[mh][3],
                             bh[nt][0], bh[nt][1]);
                }
        }
        __syncthreads();
    }

#pragma unroll
    for (int mh = 0; mh < 2; mh++)
#pragma unroll
        for (int nt = 0; nt < 4; nt++) {
            int row = m0 + wm + mh * 16 + rq;
            int col = n0 + wn + nt * 8 + kq;
            float* r0p = &C[(size_t)row * N + col];
            float* r1p = &C[(size_t)(row + 8) * N + col];
            r0p[0] = 1.0f / (1.0f + __expf(-acc[mh][nt][0]));
            r0p[1] = 1.0f / (1.0f + __expf(-acc[mh][nt][1]));
            r1p[0] = 1.0f / (1.0f + __expf(-acc[mh][nt][2]));
            r1p[1] = 1.0f / (1.0f + __expf(-acc[mh][nt][3]));
        }
}

// ---------------------------------------------------------------------------
// Launch
// ---------------------------------------------------------------------------
extern "C" void kernel_launch(void* const* d_in, const int* in_sizes, int n_in,
                              void* d_out, int out_size)
{
    const float* X_ch   = (const float*)d_in[0];
    const float* X_g    = (const float*)d_in[1];
    const float* X_d    = (const float*)d_in[2];
    const float* W_chg0 = (const float*)d_in[3];
    const float* b_chg0 = (const float*)d_in[4];
    const float* W_chg1 = (const float*)d_in[5];
    const float* b_chg1 = (const float*)d_in[6];
    const float* W_chgr = (const float*)d_in[7];
    const float* b_chgr = (const float*)d_in[8];
    const float* W_dg0  = (const float*)d_in[9];
    const float* b_dg0  = (const float*)d_in[10];
    const float* W_dg1  = (const float*)d_in[11];
    const float* b_dg1  = (const float*)d_in[12];
    const float* W_dgr  = (const float*)d_in[13];
    const float* b_dgr  = (const float*)d_in[14];

    int Nch = in_sizes[0] / D_IN;
    int Ng  = in_sizes[1] / D_IN;
    int Nd  = in_sizes[2] / D_IN;

    float* out   = (float*)d_out;
    float* A_chg = out + (size_t)Nch * Nd;
    float* A_gd  = A_chg + (size_t)Nch * Ng;

    int maxN = Nch > Ng ? Nch : Ng; if (Nd > maxN) maxN = Nd;
    precompute_kernel<<<dim3(maxN, 4), 128>>>(
        X_ch, X_g, X_d, W_chg0, b_chg0, W_dg0, b_dg0, Nch, Ng, Nd);
    w1split_kernel<<<2, 256>>>(W_chg1, W_dg1);

    cudaFuncSetAttribute(pair_mlp_mma,
                         cudaFuncAttributeMaxDynamicSharedMemorySize, SMEM_PAIR);
    cudaFuncSetAttribute(gemm_sigmoid_tc,
                         cudaFuncAttributeMaxDynamicSharedMemorySize, SMEM_GEMM);

    pair_mlp_mma<<<dim3(Ng / 128, Nch / 4, 2), 128, SMEM_PAIR>>>(
        b_chg1, W_chgr, b_chgr, A_chg,
        b_dg1,  W_dgr,  b_dgr,  A_gd, Ng);

    gemm_sigmoid_tc<<<dim3(Nd / 64, Nch / 128), 256, SMEM_GEMM>>>(
        out, Nch, Nd, Ng);
}

// round 9
// speedup vs baseline: 1.0172x; 1.0172x over previous
#include <cuda_runtime.h>
#include <cuda_bf16.h>
#include <math.h>
#include <stdint.h>

#define D_IN 5
#define H0 128
#define H1 64

// scratch: 4 arrays of [1024][128] fp32 (hl_chg, hr_chg, hl_dg, hr_dg)
__device__ float g_hbuf[4 * 1024 * 128];
// W1 hi/lo bf16, n-major padded: [branch][hi/lo][64 rows][136 cols]
__device__ __align__(16) __nv_bfloat16 g_w1[2][2][64 * 136];
// pre-split gemm operands: [op A/B][hi/lo][1024*1024] bf16
// opA = A_chg in [m][k]; opB = A_gd in [k][n]
__device__ __align__(16) __nv_bfloat16 g_ops[2][2][1024 * 1024];

// ---------------------------------------------------------------------------
// PTX helpers (architecture-portable, sm_80-level)
// ---------------------------------------------------------------------------
__device__ __forceinline__ void mma_bf16(
    float& d0, float& d1, float& d2, float& d3,
    uint32_t a0, uint32_t a1, uint32_t a2, uint32_t a3,
    uint32_t b0, uint32_t b1)
{
    asm volatile(
        "mma.sync.aligned.m16n8k16.row.col.f32.bf16.bf16.f32 "
        "{%0,%1,%2,%3}, {%4,%5,%6,%7}, {%8,%9}, {%0,%1,%2,%3};"
        : "+f"(d0), "+f"(d1), "+f"(d2), "+f"(d3)
        : "r"(a0), "r"(a1), "r"(a2), "r"(a3), "r"(b0), "r"(b1));
}

__device__ __forceinline__ void split2(float a, float b, uint32_t& hi, uint32_t& lo) {
    __nv_bfloat162 h = __float22bfloat162_rn(make_float2(a, b));
    float ra = a - __bfloat162float(h.x);
    float rb = b - __bfloat162float(h.y);
    __nv_bfloat162 l = __float22bfloat162_rn(make_float2(ra, rb));
    hi = *reinterpret_cast<uint32_t*>(&h);
    lo = *reinterpret_cast<uint32_t*>(&l);
}

__device__ __forceinline__ uint32_t smem_u32(const void* p) {
    uint32_t a;
    asm("{ .reg .u64 t; cvta.to.shared.u64 t, %1; cvt.u32.u64 %0, t; }"
        : "=r"(a) : "l"(p));
    return a;
}
__device__ __forceinline__ void cp_async16(uint32_t dst, const void* src) {
    asm volatile("cp.async.cg.shared.global [%0], [%1], 16;"
                 :: "r"(dst), "l"(src));
}
#define CP_COMMIT() asm volatile("cp.async.commit_group;" ::: "memory")
#define CP_WAIT(n)  asm volatile("cp.async.wait_group %0;" :: "n"(n) : "memory")

__device__ __forceinline__ void ldsm_x4(uint32_t& r0, uint32_t& r1,
                                        uint32_t& r2, uint32_t& r3, uint32_t a) {
    asm volatile("ldmatrix.sync.aligned.m8n8.x4.shared.b16 {%0,%1,%2,%3}, [%4];"
                 : "=r"(r0), "=r"(r1), "=r"(r2), "=r"(r3) : "r"(a));
}
__device__ __forceinline__ void ldsm_x4t(uint32_t& r0, uint32_t& r1,
                                         uint32_t& r2, uint32_t& r3, uint32_t a) {
    asm volatile("ldmatrix.sync.aligned.m8n8.x4.trans.shared.b16 {%0,%1,%2,%3}, [%4];"
                 : "=r"(r0), "=r"(r1), "=r"(r2), "=r"(r3) : "r"(a));
}
__device__ __forceinline__ uint32_t sw128(uint32_t bo) {
    return bo ^ ((bo >> 3) & 0x70);
}

// ---------------------------------------------------------------------------
// Kernel 1: precompute hl/hr for both branches (bias folded into hl)
// ---------------------------------------------------------------------------
__global__ void precompute_kernel(
    const float* __restrict__ X_ch, const float* __restrict__ X_g,
    const float* __restrict__ X_d,
    const float* __restrict__ W_chg0, const float* __restrict__ b_chg0,
    const float* __restrict__ W_dg0,  const float* __restrict__ b_dg0,
    int Nch, int Ng, int Nd)
{
    int a   = blockIdx.y;
    int row = blockIdx.x;
    int k   = threadIdx.x;

    const float* X; const float* W; const float* b = nullptr;
    int rows, woff;
    if (a == 0)      { X = X_ch; W = W_chg0; b = b_chg0; rows = Nch; woff = 0; }
    else if (a == 1) { X = X_g;  W = W_chg0;             rows = Ng;  woff = D_IN; }
    else if (a == 2) { X = X_g;  W = W_dg0;  b = b_dg0;  rows = Ng;  woff = 0; }
    else             { X = X_d;  W = W_dg0;              rows = Nd;  woff = D_IN; }
    if (row >= rows) return;

    float v = b ? b[k] : 0.0f;
#pragma unroll
    for (int d = 0; d < D_IN; d++)
        v = fmaf(X[row * D_IN + d], W[(woff + d) * H0 + k], v);
    g_hbuf[(a * 1024 + row) * H0 + k] = v;
}

// ---------------------------------------------------------------------------
// Kernel 1b: split W1 (both branches) into bf16 hi/lo, n-major padded [64][136]
// ---------------------------------------------------------------------------
__global__ void w1split_kernel(const float* __restrict__ W1a,
                               const float* __restrict__ W1b)
{
    int br = blockIdx.x;
    const float* W = br ? W1b : W1a;
    for (int i = threadIdx.x; i < 64 * 136; i += blockDim.x) {
        int n = i / 136, k = i % 136;
        float v = (k < H0) ? W[k * H1 + n] : 0.0f;
        __nv_bfloat16 h = __float2bfloat16(v);
        __nv_bfloat16 l = __float2bfloat16(v - __bfloat162float(h));
        g_w1[br][0][i] = h;
        g_w1[br][1][i] = l;
    }
}

// ---------------------------------------------------------------------------
// Kernel 2: pair MLP, bf16 3-product MMA (proven numerics), cp.async
// double-buffered shr tiles so staging overlaps compute.
// CTA = 128 threads (4 warps), warp w owns l=l0+w, 128 r's in 4 iters of 32.
// smem layout:
//   [0,17408)        W1 hi  bf16 [64][136]
//   [17408,34816)    W1 lo  bf16 [64][136]
//   [34816,69632)    shr[2] f32  [32][136] each (double buffer)
//   [69632,71680)    shl    f32  [4][128]
//   [71680,71936)    b1     f32  [64]
//   [71936,72192)    wr     f32  [64]
// ---------------------------------------------------------------------------
#define PAIR_SHR0  34816
#define PAIR_SHRSZ 17408
#define SMEM_PAIR  72192

__global__ __launch_bounds__(128, 3) void pair_mlp_mma(
    const float* __restrict__ b1a, const float* __restrict__ Wra,
    const float* __restrict__ bra, float* __restrict__ Aa,
    const float* __restrict__ b1b, const float* __restrict__ Wrb,
    const float* __restrict__ brb, float* __restrict__ Ab,
    int R)
{
    extern __shared__ char smem[];
    __nv_bfloat16* sw1hi = (__nv_bfloat16*)smem;
    __nv_bfloat16* sw1lo = (__nv_bfloat16*)(smem + 17408);
    float* shl = (float*)(smem + 69632);
    float* sb1 = (float*)(smem + 71680);
    float* swr = (float*)(smem + 71936);
    const uint32_t* w1hi32 = (const uint32_t*)sw1hi;
    const uint32_t* w1lo32 = (const uint32_t*)sw1lo;
    const uint32_t sbase = smem_u32(smem);

    const int branch = blockIdx.z;
    const float* g_hl = g_hbuf + (branch ? 2 : 0) * 1024 * H0;
    const float* g_hr = g_hbuf + (branch ? 3 : 1) * 1024 * H0;
    const float* b1 = branch ? b1b : b1a;
    const float* Wr = branch ? Wrb : Wra;
    const float* br = branch ? brb : bra;
    float* A = branch ? Ab : Aa;
    __nv_bfloat16* opHi = g_ops[branch][0];
    __nv_bfloat16* opLo = g_ops[branch][1];

    const int t    = threadIdx.x;
    const int wid  = t >> 5;
    const int lane = t & 31;
    const int l0   = blockIdx.y * 4;
    const int rblk = blockIdx.x * 128;

    // ---- stage W1 hi/lo, shl, b1, wr ----
    {
        const uint4* ghi = (const uint4*)g_w1[branch][0];
        const uint4* glo = (const uint4*)g_w1[branch][1];
        uint4* shi = (uint4*)sw1hi;
        uint4* slo = (uint4*)sw1lo;
        for (int i = t; i < 1088; i += 128) { shi[i] = ghi[i]; slo[i] = glo[i]; }
    }
    ((float4*)shl)[t] = ((const float4*)(g_hl + (size_t)l0 * H0))[t];
    if (t < H1) { sb1[t] = b1[t]; swr[t] = Wr[t]; }

    const float* shl_l = shl + wid * H0;
    const float brv = br[0];

    const int kq = (lane & 3) * 2;
    const int rq = lane >> 2;

    // stage shr tile for iteration 'riter' into buffer 'buf' via cp.async
    auto stage = [&](int riter, int buf) {
        const int rb = rblk + riter * 32;
        uint32_t dst0 = sbase + PAIR_SHR0 + buf * PAIR_SHRSZ;
#pragma unroll
        for (int i = t; i < 1024; i += 128) {
            int row = i >> 5, c4 = i & 31;
            cp_async16(dst0 + (uint32_t)(row * 136 + c4 * 4) * 4u,
                       g_hr + (size_t)(rb + row) * H0 + c4 * 4);
        }
    };

    stage(0, 0);
    CP_COMMIT();

    for (int riter = 0; riter < 4; riter++) {
        __syncthreads();   // everyone done reading buffer (riter+1)&1 from riter-1
        if (riter + 1 < 4) {
            stage(riter + 1, (riter + 1) & 1);
            CP_COMMIT();
            CP_WAIT(1);    // current buffer's group complete
        } else {
            CP_WAIT(0);
        }
        __syncthreads();   // current buffer visible to all warps

        const float* shr = (const float*)(smem + PAIR_SHR0 + (riter & 1) * PAIR_SHRSZ);
        const int rbase = rblk + riter * 32;

        float acc[2][8][4];
#pragma unroll
        for (int mh = 0; mh < 2; mh++)
#pragma unroll
            for (int nt = 0; nt < 8; nt++)
#pragma unroll
                for (int c = 0; c < 4; c++) acc[mh][nt][c] = 0.0f;

#pragma unroll
        for (int kt = 0; kt < 8; kt++) {
            const int kk = kt * 16 + kq;

            // ---- A fragments (2 m16 halves, hi+lo) ----
            uint32_t ahi[2][4], alo[2][4];
            float2 y0 = *(const float2*)(shl_l + kk);
            float2 y1 = *(const float2*)(shl_l + kk + 8);
#pragma unroll
            for (int mh = 0; mh < 2; mh++) {
                int r_lo = mh * 16 + rq;
                const float* p0 = shr + r_lo * 136 + kk;
                const float* p1 = shr + (r_lo + 8) * 136 + kk;
                float2 x00 = *(const float2*)p0;
                float2 x01 = *(const float2*)(p0 + 8);
                float2 x10 = *(const float2*)p1;
                float2 x11 = *(const float2*)(p1 + 8);
                split2(fmaxf(x00.x + y0.x, 0.f), fmaxf(x00.y + y0.y, 0.f),
                       ahi[mh][0], alo[mh][0]);
                split2(fmaxf(x10.x + y0.x, 0.f), fmaxf(x10.y + y0.y, 0.f),
                       ahi[mh][1], alo[mh][1]);
                split2(fmaxf(x01.x + y1.x, 0.f), fmaxf(x01.y + y1.y, 0.f),
                       ahi[mh][2], alo[mh][2]);
                split2(fmaxf(x11.x + y1.x, 0.f), fmaxf(x11.y + y1.y, 0.f),
                       ahi[mh][3], alo[mh][3]);
            }

            // ---- B per nt (low register pressure), 6 MMAs per 4 LDS ----
#pragma unroll
            for (int nt = 0; nt < 8; nt++) {
                int w0 = (nt * 8 + rq) * 68 + kt * 8 + (lane & 3);
                uint32_t bh0 = w1hi32[w0], bh1 = w1hi32[w0 + 4];
                uint32_t bl0 = w1lo32[w0], bl1 = w1lo32[w0 + 4];
#pragma unroll
                for (int mh = 0; mh < 2; mh++) {
                    mma_bf16(acc[mh][nt][0], acc[mh][nt][1],
                             acc[mh][nt][2], acc[mh][nt][3],
                             ahi[mh][0], ahi[mh][1], ahi[mh][2], ahi[mh][3],
                             bh0, bh1);
                    mma_bf16(acc[mh][nt][0], acc[mh][nt][1],
                             acc[mh][nt][2], acc[mh][nt][3],
                             ahi[mh][0], ahi[mh][1], ahi[mh][2], ahi[mh][3],
                             bl0, bl1);
                    mma_bf16(acc[mh][nt][0], acc[mh][nt][1],
                             acc[mh][nt][2], acc[mh][nt][3],
                             alo[mh][0], alo[mh][1], alo[mh][2], alo[mh][3],
                             bh0, bh1);
                }
            }
        }

        // epilogue: layer-2 relu/dot(Wr), quad reduce, ELU, store (f32 + bf16 split)
#pragma unroll
        for (int mh = 0; mh < 2; mh++) {
            float s0 = 0.0f, s1 = 0.0f;
#pragma unroll
            for (int nt = 0; nt < 8; nt++) {
                int j0 = nt * 8 + kq;
                float bb0 = sb1[j0], bb1 = sb1[j0 + 1];
                float ww0 = swr[j0], ww1 = swr[j0 + 1];
                s0 = fmaf(fmaxf(acc[mh][nt][0] + bb0, 0.f), ww0, s0);
                s0 = fmaf(fmaxf(acc[mh][nt][1] + bb1, 0.f), ww1, s0);
                s1 = fmaf(fmaxf(acc[mh][nt][2] + bb0, 0.f), ww0, s1);
                s1 = fmaf(fmaxf(acc[mh][nt][3] + bb1, 0.f), ww1, s1);
            }
            s0 += __shfl_xor_sync(0xffffffffu, s0, 1);
            s0 += __shfl_xor_sync(0xffffffffu, s0, 2);
            s1 += __shfl_xor_sync(0xffffffffu, s1, 1);
            s1 += __shfl_xor_sync(0xffffffffu, s1, 2);
            if ((lane & 3) == 0) {
                int r_lo = rbase + mh * 16 + rq;
                float x0 = s0 + brv;
                float x1 = s1 + brv;
                float e0 = (x0 > 0.0f) ? x0 : expm1f(x0);
                float e1 = (x1 > 0.0f) ? x1 : expm1f(x1);
                size_t rowoff = (size_t)(l0 + wid) * R;
                float* arow = A + rowoff;
                arow[r_lo]     = e0;
                arow[r_lo + 8] = e1;
                __nv_bfloat16 h0 = __float2bfloat16(e0);
                __nv_bfloat16 h1 = __float2bfloat16(e1);
                opHi[rowoff + r_lo]     = h0;
                opHi[rowoff + r_lo + 8] = h1;
                opLo[rowoff + r_lo]     = __float2bfloat16(e0 - __bfloat162float(h0));
                opLo[rowoff + r_lo + 8] = __float2bfloat16(e1 - __bfloat162float(h1));
            }
        }
    }
}

// ---------------------------------------------------------------------------
// Kernel 3: C = sigmoid(A @ B), bf16 3-product MMA, operands pre-split.
// (unchanged — 28.9us)
// ---------------------------------------------------------------------------
#define GS_STAGE 49152
#define GS_ALO   16384
#define GS_BHI   32768
#define GS_BLO   40960
#define SMEM_GEMM (2 * GS_STAGE)

__global__ __launch_bounds__(256, 1) void gemm_sigmoid_tc(
    float* __restrict__ C, int M, int N, int K)
{
    extern __shared__ char smem[];
    const uint32_t sb = smem_u32(smem);

    const __nv_bfloat16* gAhi = g_ops[0][0];
    const __nv_bfloat16* gAlo = g_ops[0][1];
    const __nv_bfloat16* gBhi = g_ops[1][0];
    const __nv_bfloat16* gBlo = g_ops[1][1];

    const int t    = threadIdx.x;
    const int wid  = t >> 5;
    const int lane = t & 31;
    const int m0 = blockIdx.y * 128, n0 = blockIdx.x * 64;
    const int wm = (wid >> 1) * 32;
    const int wn = (wid & 1) * 32;
    const int kq = (lane & 3) * 2;
    const int rq = lane >> 2;

    float acc[2][4][4];
#pragma unroll
    for (int mh = 0; mh < 2; mh++)
#pragma unroll
        for (int nt = 0; nt < 4; nt++)
#pragma unroll
            for (int c = 0; c < 4; c++) acc[mh][nt][c] = 0.0f;

    const int K64 = K >> 6;

    auto stage = [&](int kb, int buf) {
        uint32_t base = sb + buf * GS_STAGE;
#pragma unroll
        for (int i = t; i < 1024; i += 256) {
            int m = i >> 3, c = i & 7;
            uint32_t sw = sw128((uint32_t)(m * 128 + c * 16));
            size_t off = (size_t)(m0 + m) * K + kb * 64 + c * 8;
            cp_async16(base + sw, gAhi + off);
            cp_async16(base + GS_ALO + sw, gAlo + off);
        }
#pragma unroll
        for (int i = t; i < 512; i += 256) {
            int k = i >> 3, c = i & 7;
            uint32_t sw = sw128((uint32_t)(k * 128 + c * 16));
            size_t off = (size_t)(kb * 64 + k) * N + n0 + c * 8;
            cp_async16(base + GS_BHI + sw, gBhi + off);
            cp_async16(base + GS_BLO + sw, gBlo + off);
        }
    };

    stage(0, 0);
    CP_COMMIT();

    for (int kb = 0; kb < K64; kb++) {
        if (kb + 1 < K64) {
            stage(kb + 1, (kb + 1) & 1);
            CP_COMMIT();
            CP_WAIT(1);
        } else {
            CP_WAIT(0);
        }
        __syncthreads();

        uint32_t base = sb + (kb & 1) * GS_STAGE;
#pragma unroll
        for (int kt = 0; kt < 4; kt++) {
            uint32_t ahi[2][4], alo[2][4];
#pragma unroll
            for (int mh = 0; mh < 2; mh++) {
                int row = wm + mh * 16 + (lane & 15);
                uint32_t sw = sw128((uint32_t)(row * 128 + kt * 32 + (lane >> 4) * 16));
                ldsm_x4(ahi[mh][0], ahi[mh][1], ahi[mh][2], ahi[mh][3], base + sw);
                ldsm_x4(alo[mh][0], alo[mh][1], alo[mh][2], alo[mh][3],
                        base + GS_ALO + sw);
            }
            uint32_t bh[4][2], bl[4][2];
#pragma unroll
            for (int np = 0; np < 2; np++) {
                int krow = kt * 16 + (lane & 15);
                uint32_t sw = sw128((uint32_t)(krow * 128 + wn * 2 + np * 32
                                               + (lane >> 4) * 16));
                uint32_t r0, r1, r2, r3;
                ldsm_x4t(r0, r1, r2, r3, base + GS_BHI + sw);
                bh[np * 2][0] = r0; bh[np * 2][1] = r1;
                bh[np * 2 + 1][0] = r2; bh[np * 2 + 1][1] = r3;
                ldsm_x4t(r0, r1, r2, r3, base + GS_BLO + sw);
                bl[np * 2][0] = r0; bl[np * 2][1] = r1;
                bl[np * 2 + 1][0] = r2; bl[np * 2 + 1][1] = r3;
            }
#pragma unroll
            for (int nt = 0; nt < 4; nt++)
#pragma unroll
                for (int mh = 0; mh < 2; mh++) {
                    mma_bf16(acc[mh][nt][0], acc[mh][nt][1],
                             acc[mh][nt][2], acc[mh][nt][3],
                             ahi[mh][0], ahi[mh][1], ahi[mh][2], ahi[mh][3],
                             bh[nt][0], bh[nt][1]);
                    mma_bf16(acc[mh][nt][0], acc[mh][nt][1],
                             acc[mh][nt][2], acc[mh][nt][3],
                             ahi[mh][0], ahi[mh][1], ahi[mh][2], ahi[mh][3],
                             bl[nt][0], bl[nt][1]);
                    mma_bf16(acc[mh][nt][0], acc[mh][nt][1],
                             acc[mh][nt][2], acc[mh][nt][3],
                             alo[mh][0], alo[mh][1], alo[mh][2], alo[mh][3],
                             bh[nt][0], bh[nt][1]);
                }
        }
        __syncthreads();
    }

#pragma unroll
    for (int mh = 0; mh < 2; mh++)
#pragma unroll
        for (int nt = 0; nt < 4; nt++) {
            int row = m0 + wm + mh * 16 + rq;
            int col = n0 + wn + nt * 8 + kq;
            float* r0p = &C[(size_t)row * N + col];
            float* r1p = &C[(size_t)(row + 8) * N + col];
            r0p[0] = 1.0f / (1.0f + __expf(-acc[mh][nt][0]));
            r0p[1] = 1.0f / (1.0f + __expf(-acc[mh][nt][1]));
            r1p[0] = 1.0f / (1.0f + __expf(-acc[mh][nt][2]));
            r1p[1] = 1.0f / (1.0f + __expf(-acc[mh][nt][3]));
        }
}

// ---------------------------------------------------------------------------
// Launch
// ---------------------------------------------------------------------------
extern "C" void kernel_launch(void* const* d_in, const int* in_sizes, int n_in,
                              void* d_out, int out_size)
{
    const float* X_ch   = (const float*)d_in[0];
    const float* X_g    = (const float*)d_in[1];
    const float* X_d    = (const float*)d_in[2];
    const float* W_chg0 = (const float*)d_in[3];
    const float* b_chg0 = (const float*)d_in[4];
    const float* W_chg1 = (const float*)d_in[5];
    const float* b_chg1 = (const float*)d_in[6];
    const float* W_chgr = (const float*)d_in[7];
    const float* b_chgr = (const float*)d_in[8];
    const float* W_dg0  = (const float*)d_in[9];
    const float* b_dg0  = (const float*)d_in[10];
    const float* W_dg1  = (const float*)d_in[11];
    const float* b_dg1  = (const float*)d_in[12];
    const float* W_dgr  = (const float*)d_in[13];
    const float* b_dgr  = (const float*)d_in[14];

    int Nch = in_sizes[0] / D_IN;
    int Ng  = in_sizes[1] / D_IN;
    int Nd  = in_sizes[2] / D_IN;

    float* out   = (float*)d_out;
    float* A_chg = out + (size_t)Nch * Nd;
    float* A_gd  = A_chg + (size_t)Nch * Ng;

    int maxN = Nch > Ng ? Nch : Ng; if (Nd > maxN) maxN = Nd;
    precompute_kernel<<<dim3(maxN, 4), 128>>>(
        X_ch, X_g, X_d, W_chg0, b_chg0, W_dg0, b_dg0, Nch, Ng, Nd);
    w1split_kernel<<<2, 256>>>(W_chg1, W_dg1);

    cudaFuncSetAttribute(pair_mlp_mma,
                         cudaFuncAttributeMaxDynamicSharedMemorySize, SMEM_PAIR);
    cudaFuncSetAttribute(gemm_sigmoid_tc,
                         cudaFuncAttributeMaxDynamicSharedMemorySize, SMEM_GEMM);

    pair_mlp_mma<<<dim3(Ng / 128, Nch / 4, 2), 128, SMEM_PAIR>>>(
        b_chg1, W_chgr, b_chgr, A_chg,
        b_dg1,  W_dgr,  b_dgr,  A_gd, Ng);

    gemm_sigmoid_tc<<<dim3(Nd / 64, Nch / 128), 256, SMEM_GEMM>>>(
        out, Nch, Nd, Ng);
}

// round 10
// speedup vs baseline: 1.0220x; 1.0047x over previous
#include <cuda_runtime.h>
#include <cuda_bf16.h>
#include <math.h>
#include <stdint.h>

#define D_IN 5
#define H0 128
#define H1 64

// scratch: 4 arrays of [1024][128] fp32 (hl_chg, hr_chg, hl_dg, hr_dg)
__device__ float g_hbuf[4 * 1024 * 128];
// W1 hi/lo bf16, n-major padded: [branch][hi/lo][64 rows][136 cols]
__device__ __align__(16) __nv_bfloat16 g_w1[2][2][64 * 136];
// pre-split gemm operands: [op A/B][hi/lo][1024*1024] bf16
__device__ __align__(16) __nv_bfloat16 g_ops[2][2][1024 * 1024];

// ---------------------------------------------------------------------------
// PTX helpers (architecture-portable, sm_80-level)
// ---------------------------------------------------------------------------
__device__ __forceinline__ void mma_bf16(
    float& d0, float& d1, float& d2, float& d3,
    uint32_t a0, uint32_t a1, uint32_t a2, uint32_t a3,
    uint32_t b0, uint32_t b1)
{
    asm volatile(
        "mma.sync.aligned.m16n8k16.row.col.f32.bf16.bf16.f32 "
        "{%0,%1,%2,%3}, {%4,%5,%6,%7}, {%8,%9}, {%0,%1,%2,%3};"
        : "+f"(d0), "+f"(d1), "+f"(d2), "+f"(d3)
        : "r"(a0), "r"(a1), "r"(a2), "r"(a3), "r"(b0), "r"(b1));
}

__device__ __forceinline__ void split2(float a, float b, uint32_t& hi, uint32_t& lo) {
    __nv_bfloat162 h = __float22bfloat162_rn(make_float2(a, b));
    float ra = a - __bfloat162float(h.x);
    float rb = b - __bfloat162float(h.y);
    __nv_bfloat162 l = __float22bfloat162_rn(make_float2(ra, rb));
    hi = *reinterpret_cast<uint32_t*>(&h);
    lo = *reinterpret_cast<uint32_t*>(&l);
}

__device__ __forceinline__ uint32_t smem_u32(const void* p) {
    uint32_t a;
    asm("{ .reg .u64 t; cvta.to.shared.u64 t, %1; cvt.u32.u64 %0, t; }"
        : "=r"(a) : "l"(p));
    return a;
}
__device__ __forceinline__ void cp_async16(uint32_t dst, const void* src) {
    asm volatile("cp.async.cg.shared.global [%0], [%1], 16;"
                 :: "r"(dst), "l"(src));
}
#define CP_COMMIT() asm volatile("cp.async.commit_group;" ::: "memory")
#define CP_WAIT(n)  asm volatile("cp.async.wait_group %0;" :: "n"(n) : "memory")

__device__ __forceinline__ void ldsm_x4(uint32_t& r0, uint32_t& r1,
                                        uint32_t& r2, uint32_t& r3, uint32_t a) {
    asm volatile("ldmatrix.sync.aligned.m8n8.x4.shared.b16 {%0,%1,%2,%3}, [%4];"
                 : "=r"(r0), "=r"(r1), "=r"(r2), "=r"(r3) : "r"(a));
}
__device__ __forceinline__ void ldsm_x4t(uint32_t& r0, uint32_t& r1,
                                         uint32_t& r2, uint32_t& r3, uint32_t a) {
    asm volatile("ldmatrix.sync.aligned.m8n8.x4.trans.shared.b16 {%0,%1,%2,%3}, [%4];"
                 : "=r"(r0), "=r"(r1), "=r"(r2), "=r"(r3) : "r"(a));
}
__device__ __forceinline__ uint32_t sw128(uint32_t bo) {
    return bo ^ ((bo >> 3) & 0x70);
}

// ---------------------------------------------------------------------------
// Kernel 1: precompute hl/hr for both branches (bias folded into hl)
// ---------------------------------------------------------------------------
__global__ void precompute_kernel(
    const float* __restrict__ X_ch, const float* __restrict__ X_g,
    const float* __restrict__ X_d,
    const float* __restrict__ W_chg0, const float* __restrict__ b_chg0,
    const float* __restrict__ W_dg0,  const float* __restrict__ b_dg0,
    int Nch, int Ng, int Nd)
{
    int a   = blockIdx.y;
    int row = blockIdx.x;
    int k   = threadIdx.x;

    const float* X; const float* W; const float* b = nullptr;
    int rows, woff;
    if (a == 0)      { X = X_ch; W = W_chg0; b = b_chg0; rows = Nch; woff = 0; }
    else if (a == 1) { X = X_g;  W = W_chg0;             rows = Ng;  woff = D_IN; }
    else if (a == 2) { X = X_g;  W = W_dg0;  b = b_dg0;  rows = Ng;  woff = 0; }
    else             { X = X_d;  W = W_dg0;              rows = Nd;  woff = D_IN; }
    if (row >= rows) return;

    float v = b ? b[k] : 0.0f;
#pragma unroll
    for (int d = 0; d < D_IN; d++)
        v = fmaf(X[row * D_IN + d], W[(woff + d) * H0 + k], v);
    g_hbuf[(a * 1024 + row) * H0 + k] = v;
}

// ---------------------------------------------------------------------------
// Kernel 1b: split W1 (both branches) into bf16 hi/lo, n-major padded [64][136]
// ---------------------------------------------------------------------------
__global__ void w1split_kernel(const float* __restrict__ W1a,
                               const float* __restrict__ W1b)
{
    int br = blockIdx.x;
    const float* W = br ? W1b : W1a;
    for (int i = threadIdx.x; i < 64 * 136; i += blockDim.x) {
        int n = i / 136, k = i % 136;
        float v = (k < H0) ? W[k * H1 + n] : 0.0f;
        __nv_bfloat16 h = __float2bfloat16(v);
        __nv_bfloat16 l = __float2bfloat16(v - __bfloat162float(h));
        g_w1[br][0][i] = h;
        g_w1[br][1][i] = l;
    }
}

// ---------------------------------------------------------------------------
// Kernel 2: pair MLP, bf16 3-product MMA. CTA = 256 threads (8 warps) =
// 4 l-values x 2 r-halves; each warp: 16 pairs x 64 n (acc 32 regs).
// B fragments via ldmatrix.x4; shr tiles cp.async double-buffered.
// smem layout:
//   [0,17408)      W1 hi bf16 [64][136]
//   [17408,34816)  W1 lo bf16 [64][136]
//   [34816,69632)  shr[2] f32 [32][136]
//   [69632,73728)  shl f32 [4][128]
//   [73728,73984)  b1 | [73984,74240) wr
// ---------------------------------------------------------------------------
#define PAIR_SHR0  34816
#define PAIR_SHRSZ 17408
#define SMEM_PAIR  74240

__global__ __launch_bounds__(256, 3) void pair_mlp_mma(
    const float* __restrict__ b1a, const float* __restrict__ Wra,
    const float* __restrict__ bra, float* __restrict__ Aa,
    const float* __restrict__ b1b, const float* __restrict__ Wrb,
    const float* __restrict__ brb, float* __restrict__ Ab,
    int R)
{
    extern __shared__ char smem[];
    __nv_bfloat16* sw1hi = (__nv_bfloat16*)smem;
    float* shl = (float*)(smem + 69632);
    float* sb1 = (float*)(smem + 73728);
    float* swr = (float*)(smem + 73984);
    const uint32_t sbase = smem_u32(smem);

    const int branch = blockIdx.z;
    const float* g_hl = g_hbuf + (branch ? 2 : 0) * 1024 * H0;
    const float* g_hr = g_hbuf + (branch ? 3 : 1) * 1024 * H0;
    const float* b1 = branch ? b1b : b1a;
    const float* Wr = branch ? Wrb : Wra;
    const float* br = branch ? brb : bra;
    float* A = branch ? Ab : Aa;
    __nv_bfloat16* opHi = g_ops[branch][0];
    __nv_bfloat16* opLo = g_ops[branch][1];

    const int t    = threadIdx.x;
    const int wid  = t >> 5;
    const int lane = t & 31;
    const int lw   = wid >> 1;     // l index within CTA (0..3)
    const int rh   = wid & 1;      // r-half (0..1), 16 pairs each
    const int l0   = blockIdx.y * 4;
    const int rblk = blockIdx.x * 128;

    // ---- stage W1 hi/lo (both arrays contiguous: 2176 uint4), shl, b1, wr ----
    {
        const uint4* gw = (const uint4*)g_w1[branch][0];
        uint4* sw = (uint4*)sw1hi;
        for (int i = t; i < 2176; i += 256) sw[i] = gw[i];
    }
    if (t < 128) ((float4*)shl)[t] = ((const float4*)(g_hl + (size_t)l0 * H0))[t];
    if (t >= 128 && t < 128 + H1) { sb1[t - 128] = b1[t - 128]; swr[t - 128] = Wr[t - 128]; }

    const float* shl_l = shl + lw * H0;
    const float brv = br[0];

    const int kq = (lane & 3) * 2;
    const int rq = lane >> 2;

    // ldmatrix lane address components for B (W1) fragments
    const int btile = lane >> 3;            // 0..3
    const int bnoff = (btile >> 1) * 8 + (lane & 7);   // row within 16-n group
    const int bkoff = (btile & 1) * 8;                 // k-half within k16

    // stage shr tile for iteration 'riter' into buffer 'buf' via cp.async
    auto stage = [&](int riter, int buf) {
        const int rb = rblk + riter * 32;
        uint32_t dst0 = sbase + PAIR_SHR0 + buf * PAIR_SHRSZ;
#pragma unroll
        for (int i = t; i < 1024; i += 256) {
            int row = i >> 5, c4 = i & 31;
            cp_async16(dst0 + (uint32_t)(row * 136 + c4 * 4) * 4u,
                       g_hr + (size_t)(rb + row) * H0 + c4 * 4);
        }
    };

    stage(0, 0);
    CP_COMMIT();

    for (int riter = 0; riter < 4; riter++) {
        __syncthreads();
        if (riter + 1 < 4) {
            stage(riter + 1, (riter + 1) & 1);
            CP_COMMIT();
            CP_WAIT(1);
        } else {
            CP_WAIT(0);
        }
        __syncthreads();

        const float* shr = (const float*)(smem + PAIR_SHR0 + (riter & 1) * PAIR_SHRSZ);
        const int rbase = rblk + riter * 32;

        float acc[8][4];
#pragma unroll
        for (int nt = 0; nt < 8; nt++)
#pragma unroll
            for (int c = 0; c < 4; c++) acc[nt][c] = 0.0f;

#pragma unroll
        for (int kt = 0; kt < 8; kt++) {
            const int kk = kt * 16 + kq;

            // ---- A fragments: relu(hl+hr) split hi/lo (this warp's 16 pairs) ----
            uint32_t ahi[4], alo[4];
            {
                float2 y0 = *(const float2*)(shl_l + kk);
                float2 y1 = *(const float2*)(shl_l + kk + 8);
                int r_lo = rh * 16 + rq;
                const float* p0 = shr + r_lo * 136 + kk;
                const float* p1 = shr + (r_lo + 8) * 136 + kk;
                float2 x00 = *(const float2*)p0;
                float2 x01 = *(const float2*)(p0 + 8);
                float2 x10 = *(const float2*)p1;
                float2 x11 = *(const float2*)(p1 + 8);
                split2(fmaxf(x00.x + y0.x, 0.f), fmaxf(x00.y + y0.y, 0.f),
                       ahi[0], alo[0]);
                split2(fmaxf(x10.x + y0.x, 0.f), fmaxf(x10.y + y0.y, 0.f),
                       ahi[1], alo[1]);
                split2(fmaxf(x01.x + y1.x, 0.f), fmaxf(x01.y + y1.y, 0.f),
                       ahi[2], alo[2]);
                split2(fmaxf(x11.x + y1.x, 0.f), fmaxf(x11.y + y1.y, 0.f),
                       ahi[3], alo[3]);
            }

            // ---- B fragments via ldmatrix.x4: 2 n-tiles per call ----
#pragma unroll
            for (int g = 0; g < 4; g++) {
                uint32_t boff = (uint32_t)((g * 16 + bnoff) * 136
                                           + kt * 16 + bkoff) * 2u;
                uint32_t bh0, bh1, bh2, bh3, bl0, bl1, bl2, bl3;
                ldsm_x4(bh0, bh1, bh2, bh3, sbase + boff);
                ldsm_x4(bl0, bl1, bl2, bl3, sbase + 17408u + boff);

                int nt0 = 2 * g, nt1 = 2 * g + 1;
                mma_bf16(acc[nt0][0], acc[nt0][1], acc[nt0][2], acc[nt0][3],
                         ahi[0], ahi[1], ahi[2], ahi[3], bh0, bh1);
                mma_bf16(acc[nt0][0], acc[nt0][1], acc[nt0][2], acc[nt0][3],
                         ahi[0], ahi[1], ahi[2], ahi[3], bl0, bl1);
                mma_bf16(acc[nt0][0], acc[nt0][1], acc[nt0][2], acc[nt0][3],
                         alo[0], alo[1], alo[2], alo[3], bh0, bh1);
                mma_bf16(acc[nt1][0], acc[nt1][1], acc[nt1][2], acc[nt1][3],
                         ahi[0], ahi[1], ahi[2], ahi[3], bh2, bh3);
                mma_bf16(acc[nt1][0], acc[nt1][1], acc[nt1][2], acc[nt1][3],
                         ahi[0], ahi[1], ahi[2], ahi[3], bl2, bl3);
                mma_bf16(acc[nt1][0], acc[nt1][1], acc[nt1][2], acc[nt1][3],
                         alo[0], alo[1], alo[2], alo[3], bh2, bh3);
            }
        }

        // ---- epilogue: layer-2 relu/dot(Wr), quad reduce, ELU, store ----
        {
            float s0 = 0.0f, s1 = 0.0f;
#pragma unroll
            for (int nt = 0; nt < 8; nt++) {
                int j0 = nt * 8 + kq;
                float bb0 = sb1[j0], bb1 = sb1[j0 + 1];
                float ww0 = swr[j0], ww1 = swr[j0 + 1];
                s0 = fmaf(fmaxf(acc[nt][0] + bb0, 0.f), ww0, s0);
                s0 = fmaf(fmaxf(acc[nt][1] + bb1, 0.f), ww1, s0);
                s1 = fmaf(fmaxf(acc[nt][2] + bb0, 0.f), ww0, s1);
                s1 = fmaf(fmaxf(acc[nt][3] + bb1, 0.f), ww1, s1);
            }
            s0 += __shfl_xor_sync(0xffffffffu, s0, 1);
            s0 += __shfl_xor_sync(0xffffffffu, s0, 2);
            s1 += __shfl_xor_sync(0xffffffffu, s1, 1);
            s1 += __shfl_xor_sync(0xffffffffu, s1, 2);
            if ((lane & 3) == 0) {
                int r_lo = rbase + rh * 16 + rq;
                float x0 = s0 + brv;
                float x1 = s1 + brv;
                float e0 = (x0 > 0.0f) ? x0 : expm1f(x0);
                float e1 = (x1 > 0.0f) ? x1 : expm1f(x1);
                size_t rowoff = (size_t)(l0 + lw) * R;
                float* arow = A + rowoff;
                arow[r_lo]     = e0;
                arow[r_lo + 8] = e1;
                __nv_bfloat16 h0 = __float2bfloat16(e0);
                __nv_bfloat16 h1 = __float2bfloat16(e1);
                opHi[rowoff + r_lo]     = h0;
                opHi[rowoff + r_lo + 8] = h1;
                opLo[rowoff + r_lo]     = __float2bfloat16(e0 - __bfloat162float(h0));
                opLo[rowoff + r_lo + 8] = __float2bfloat16(e1 - __bfloat162float(h1));
            }
        }
    }
}

// ---------------------------------------------------------------------------
// Kernel 3: C = sigmoid(A @ B), bf16 3-product MMA, operands pre-split.
// (unchanged — 28.9us)
// ---------------------------------------------------------------------------
#define GS_STAGE 49152
#define GS_ALO   16384
#define GS_BHI   32768
#define GS_BLO   40960
#define SMEM_GEMM (2 * GS_STAGE)

__global__ __launch_bounds__(256, 1) void gemm_sigmoid_tc(
    float* __restrict__ C, int M, int N, int K)
{
    extern __shared__ char smem[];
    const uint32_t sb = smem_u32(smem);

    const __nv_bfloat16* gAhi = g_ops[0][0];
    const __nv_bfloat16* gAlo = g_ops[0][1];
    const __nv_bfloat16* gBhi = g_ops[1][0];
    const __nv_bfloat16* gBlo = g_ops[1][1];

    const int t    = threadIdx.x;
    const int wid  = t >> 5;
    const int lane = t & 31;
    const int m0 = blockIdx.y * 128, n0 = blockIdx.x * 64;
    const int wm = (wid >> 1) * 32;
    const int wn = (wid & 1) * 32;
    const int kq = (lane & 3) * 2;
    const int rq = lane >> 2;

    float acc[2][4][4];
#pragma unroll
    for (int mh = 0; mh < 2; mh++)
#pragma unroll
        for (int nt = 0; nt < 4; nt++)
#pragma unroll
            for (int c = 0; c < 4; c++) acc[mh][nt][c] = 0.0f;

    const int K64 = K >> 6;

    auto stage = [&](int kb, int buf) {
        uint32_t base = sb + buf * GS_STAGE;
#pragma unroll
        for (int i = t; i < 1024; i += 256) {
            int m = i >> 3, c = i & 7;
            uint32_t sw = sw128((uint32_t)(m * 128 + c * 16));
            size_t off = (size_t)(m0 + m) * K + kb * 64 + c * 8;
            cp_async16(base + sw, gAhi + off);
            cp_async16(base + GS_ALO + sw, gAlo + off);
        }
#pragma unroll
        for (int i = t; i < 512; i += 256) {
            int k = i >> 3, c = i & 7;
            uint32_t sw = sw128((uint32_t)(k * 128 + c * 16));
            size_t off = (size_t)(kb * 64 + k) * N + n0 + c * 8;
            cp_async16(base + GS_BHI + sw, gBhi + off);
            cp_async16(base + GS_BLO + sw, gBlo + off);
        }
    };

    stage(0, 0);
    CP_COMMIT();

    for (int kb = 0; kb < K64; kb++) {
        if (kb + 1 < K64) {
            stage(kb + 1, (kb + 1) & 1);
            CP_COMMIT();
            CP_WAIT(1);
        } else {
            CP_WAIT(0);
        }
        __syncthreads();

        uint32_t base = sb + (kb & 1) * GS_STAGE;
#pragma unroll
        for (int kt = 0; kt < 4; kt++) {
            uint32_t ahi[2][4], alo[2][4];
#pragma unroll
            for (int mh = 0; mh < 2; mh++) {
                int row = wm + mh * 16 + (lane & 15);
                uint32_t sw = sw128((uint32_t)(row * 128 + kt * 32 + (lane >> 4) * 16));
                ldsm_x4(ahi[mh][0], ahi[mh][1], ahi[mh][2], ahi[mh][3], base + sw);
                ldsm_x4(alo[mh][0], alo[mh][1], alo[mh][2], alo[mh][3],
                        base + GS_ALO + sw);
            }
            uint32_t bh[4][2], bl[4][2];
#pragma unroll
            for (int np = 0; np < 2; np++) {
                int krow = kt * 16 + (lane & 15);
                uint32_t sw = sw128((uint32_t)(krow * 128 + wn * 2 + np * 32
                                               + (lane >> 4) * 16));
                uint32_t r0, r1, r2, r3;
                ldsm_x4t(r0, r1, r2, r3, base + GS_BHI + sw);
                bh[np * 2][0] = r0; bh[np * 2][1] = r1;
                bh[np * 2 + 1][0] = r2; bh[np * 2 + 1][1] = r3;
                ldsm_x4t(r0, r1, r2, r3, base + GS_BLO + sw);
                bl[np * 2][0] = r0; bl[np * 2][1] = r1;
                bl[np * 2 + 1][0] = r2; bl[np * 2 + 1][1] = r3;
            }
#pragma unroll
            for (int nt = 0; nt < 4; nt++)
#pragma unroll
                for (int mh = 0; mh < 2; mh++) {
                    mma_bf16(acc[mh][nt][0], acc[mh][nt][1],
                             acc[mh][nt][2], acc[mh][nt][3],
                             ahi[mh][0], ahi[mh][1], ahi[mh][2], ahi[mh][3],
                             bh[nt][0], bh[nt][1]);
                    mma_bf16(acc[mh][nt][0], acc[mh][nt][1],
                             acc[mh][nt][2], acc[mh][nt][3],
                             ahi[mh][0], ahi[mh][1], ahi[mh][2], ahi[mh][3],
                             bl[nt][0], bl[nt][1]);
                    mma_bf16(acc[mh][nt][0], acc[mh][nt][1],
                             acc[mh][nt][2], acc[mh][nt][3],
                             alo[mh][0], alo[mh][1], alo[mh][2], alo[mh][3],
                             bh[nt][0], bh[nt][1]);
                }
        }
        __syncthreads();
    }

#pragma unroll
    for (int mh = 0; mh < 2; mh++)
#pragma unroll
        for (int nt = 0; nt < 4; nt++) {
            int row = m0 + wm + mh * 16 + rq;
            int col = n0 + wn + nt * 8 + kq;
            float* r0p = &C[(size_t)row * N + col];
            float* r1p = &C[(size_t)(row + 8) * N + col];
            r0p[0] = 1.0f / (1.0f + __expf(-acc[mh][nt][0]));
            r0p[1] = 1.0f / (1.0f + __expf(-acc[mh][nt][1]));
            r1p[0] = 1.0f / (1.0f + __expf(-acc[mh][nt][2]));
            r1p[1] = 1.0f / (1.0f + __expf(-acc[mh][nt][3]));
        }
}

// ---------------------------------------------------------------------------
// Launch
// ---------------------------------------------------------------------------
extern "C" void kernel_launch(void* const* d_in, const int* in_sizes, int n_in,
                              void* d_out, int out_size)
{
    const float* X_ch   = (const float*)d_in[0];
    const float* X_g    = (const float*)d_in[1];
    const float* X_d    = (const float*)d_in[2];
    const float* W_chg0 = (const float*)d_in[3];
    const float* b_chg0 = (const float*)d_in[4];
    const float* W_chg1 = (const float*)d_in[5];
    const float* b_chg1 = (const float*)d_in[6];
    const float* W_chgr = (const float*)d_in[7];
    const float* b_chgr = (const float*)d_in[8];
    const float* W_dg0  = (const float*)d_in[9];
    const float* b_dg0  = (const float*)d_in[10];
    const float* W_dg1  = (const float*)d_in[11];
    const float* b_dg1  = (const float*)d_in[12];
    const float* W_dgr  = (const float*)d_in[13];
    const float* b_dgr  = (const float*)d_in[14];

    int Nch = in_sizes[0] / D_IN;
    int Ng  = in_sizes[1] / D_IN;
    int Nd  = in_sizes[2] / D_IN;

    float* out   = (float*)d_out;
    float* A_chg = out + (size_t)Nch * Nd;
    float* A_gd  = A_chg + (size_t)Nch * Ng;

    int maxN = Nch > Ng ? Nch : Ng; if (Nd > maxN) maxN = Nd;
    precompute_kernel<<<dim3(maxN, 4), 128>>>(
        X_ch, X_g, X_d, W_chg0, b_chg0, W_dg0, b_dg0, Nch, Ng, Nd);
    w1split_kernel<<<2, 256>>>(W_chg1, W_dg1);

    cudaFuncSetAttribute(pair_mlp_mma,
                         cudaFuncAttributeMaxDynamicSharedMemorySize, SMEM_PAIR);
    cudaFuncSetAttribute(gemm_sigmoid_tc,
                         cudaFuncAttributeMaxDynamicSharedMemorySize, SMEM_GEMM);

    pair_mlp_mma<<<dim3(Ng / 128, Nch / 4, 2), 256, SMEM_PAIR>>>(
        b_chg1, W_chgr, b_chgr, A_chg,
        b_dg1,  W_dgr,  b_dgr,  A_gd, Ng);

    gemm_sigmoid_tc<<<dim3(Nd / 64, Nch / 128), 256, SMEM_GEMM>>>(
        out, Nch, Nd, Ng);
}